// round 3
// baseline (speedup 1.0000x reference)
#include <cuda_runtime.h>
#include <math.h>

#define NMAX 50000
#define EMAX 800000

// ---------------- scratch (no allocation allowed) ----------------
__device__ __align__(16) int   g_cnt[NMAX];        // in-degree (counting-sort hist)
__device__ __align__(16) int   g_rp[NMAX];         // CSR row ptr (per-block exclusive scan)
__device__ __align__(16) int   g_ofs[NMAX];        // fill cursors
__device__ __align__(16) int   g_bsum[64];         // scan block sums
__device__ __align__(16) float g_dinv[NMAX];
__device__ __align__(16) int   g_csr[EMAX];        // src index only
__device__ __align__(16) float g_y[4 * NMAX * 16]; // layer-1 projections y_k
__device__ __align__(16) float g_t[NMAX * 16];
__device__ __align__(16) float g_u[NMAX * 16];
__device__ __align__(16) float g_G[4 * NMAX * 16]; // layer-2 hops

// ---------------- CSR build ----------------
__global__ void k_zero1(int* __restrict__ a, int n) {
  int i = blockIdx.x * blockDim.x + threadIdx.x;
  if (i < n) a[i] = 0;
}

__global__ void k_hist(const int* __restrict__ ei, int* __restrict__ cnt, int E) {
  int e = blockIdx.x * blockDim.x + threadIdx.x;
  if (e < E) atomicAdd(&cnt[ei[E + e]], 1);
}

// per-1024-block exclusive scan via warp shuffles; also emits dinv and zeroes ofs
__global__ __launch_bounds__(1024) void k_scan1(const int* __restrict__ cnt,
                                                int* __restrict__ rp,
                                                int* __restrict__ bsum,
                                                float* __restrict__ dinv,
                                                int* __restrict__ ofs, int n) {
  __shared__ int ws[32];
  int t = threadIdx.x;
  int i = blockIdx.x * 1024 + t;
  int c = (i < n) ? cnt[i] : 0;
  if (i < n) {
    dinv[i] = (c > 0) ? rsqrtf((float)c) : 0.f;
    ofs[i] = 0;
  }
  int s = c;
  #pragma unroll
  for (int o = 1; o < 32; o <<= 1) {
    int p = __shfl_up_sync(0xffffffffu, s, o);
    if ((t & 31) >= o) s += p;
  }
  if ((t & 31) == 31) ws[t >> 5] = s;
  __syncthreads();
  if (t < 32) {
    int b = ws[t];
    int sb = b;
    #pragma unroll
    for (int o = 1; o < 32; o <<= 1) {
      int p = __shfl_up_sync(0xffffffffu, sb, o);
      if (t >= o) sb += p;
    }
    ws[t] = sb - b;               // exclusive warp offset
    if (t == 31) bsum[blockIdx.x] = sb;  // block total
  }
  __syncthreads();
  if (i < n) rp[i] = (s - c) + ws[t >> 5];
}

// scan up to 64 block sums in one block (exclusive, in place)
__global__ void k_scan2(int* __restrict__ bsum, int nb) {
  __shared__ int sh[64];
  int t = threadIdx.x;
  int v = (t < nb) ? bsum[t] : 0;
  sh[t] = v;
  __syncthreads();
  #pragma unroll
  for (int o = 1; o < 64; o <<= 1) {
    int p = (t >= o) ? sh[t - o] : 0;
    __syncthreads();
    sh[t] += p;
    __syncthreads();
  }
  if (t < nb) bsum[t] = sh[t] - v;
}

// fill CSR: src indices sorted into dst buckets (weights derived from dinv later)
__global__ void k_fill(const int* __restrict__ ei, const int* __restrict__ rp,
                       const int* __restrict__ bsum, int* __restrict__ ofs,
                       int* __restrict__ csr, int E) {
  int e = blockIdx.x * blockDim.x + threadIdx.x;
  if (e >= E) return;
  int s = ei[e];
  int d = ei[E + e];
  int p = __ldg(&rp[d]) + __ldg(&bsum[d >> 10]) + atomicAdd(&ofs[d], 1);
  csr[p] = s;
}

// ---------------- gather SpMM ----------------
// out[r] = epi( init[r] + dinv[r] * sum_e dinv[src_e] * in[src_e] )
// 4 threads per row (one float4 quad each); init==null -> no add; bias -> +b, ReLU.
__global__ __launch_bounds__(256) void k_spmm(
    const int* __restrict__ rp, const int* __restrict__ cnt,
    const int* __restrict__ bsum, const int* __restrict__ csr,
    const float* __restrict__ dinv, const float4* __restrict__ in,
    const float4* __restrict__ init, const float* __restrict__ bias,
    float4* __restrict__ out, int n) {
  int idx = blockIdx.x * blockDim.x + threadIdx.x;
  int r = idx >> 2;
  if (r >= n) return;
  int q = idx & 3;
  int start = __ldg(&rp[r]) + __ldg(&bsum[r >> 10]);
  int len = __ldg(&cnt[r]);
  float4 a0 = make_float4(0.f, 0.f, 0.f, 0.f);
  float4 a1 = make_float4(0.f, 0.f, 0.f, 0.f);
  int i = 0;
  for (; i + 4 <= len; i += 4) {
    int s0 = __ldg(&csr[start + i + 0]);
    int s1 = __ldg(&csr[start + i + 1]);
    int s2 = __ldg(&csr[start + i + 2]);
    int s3 = __ldg(&csr[start + i + 3]);
    float w0 = __ldg(&dinv[s0]);
    float w1 = __ldg(&dinv[s1]);
    float w2 = __ldg(&dinv[s2]);
    float w3 = __ldg(&dinv[s3]);
    float4 v0 = __ldg(&in[(s0 << 2) + q]);
    float4 v1 = __ldg(&in[(s1 << 2) + q]);
    float4 v2 = __ldg(&in[(s2 << 2) + q]);
    float4 v3 = __ldg(&in[(s3 << 2) + q]);
    a0.x += w0 * v0.x; a0.y += w0 * v0.y; a0.z += w0 * v0.z; a0.w += w0 * v0.w;
    a1.x += w1 * v1.x; a1.y += w1 * v1.y; a1.z += w1 * v1.z; a1.w += w1 * v1.w;
    a0.x += w2 * v2.x; a0.y += w2 * v2.y; a0.z += w2 * v2.z; a0.w += w2 * v2.w;
    a1.x += w3 * v3.x; a1.y += w3 * v3.y; a1.z += w3 * v3.z; a1.w += w3 * v3.w;
  }
  for (; i < len; i++) {
    int s0 = __ldg(&csr[start + i]);
    float w0 = __ldg(&dinv[s0]);
    float4 v0 = __ldg(&in[(s0 << 2) + q]);
    a0.x += w0 * v0.x; a0.y += w0 * v0.y; a0.z += w0 * v0.z; a0.w += w0 * v0.w;
  }
  float dr = __ldg(&dinv[r]);
  float4 acc = make_float4(dr * (a0.x + a1.x), dr * (a0.y + a1.y),
                           dr * (a0.z + a1.z), dr * (a0.w + a1.w));
  if (init) {
    float4 iv = init[(r << 2) + q];
    acc.x += iv.x; acc.y += iv.y; acc.z += iv.z; acc.w += iv.w;
  }
  if (bias) {
    float4 bb = ((const float4*)bias)[q];
    acc = make_float4(fmaxf(acc.x + bb.x, 0.f), fmaxf(acc.y + bb.y, 0.f),
                      fmaxf(acc.z + bb.z, 0.f), fmaxf(acc.w + bb.w, 0.f));
  }
  out[(r << 2) + q] = acc;
}

// ---------------- GEMM1: y[k][n][16] = (x/rowsum) @ W1[k], rowsum fused ----------------
__global__ __launch_bounds__(256) void k_gemm1(
    const float* __restrict__ x, const float* __restrict__ W1,
    float* __restrict__ y, int n) {
  __shared__ float Ws[128][64];
  __shared__ float Xs[128][16];
  int tid = threadIdx.x;
  int rowBase = blockIdx.x * 128;
  for (int s = tid; s < 8192; s += 256) {
    int d = s >> 6, c = s & 63;
    Ws[d][c] = W1[(((c >> 4) << 7) | d) * 16 + (c & 15)];
  }
  float4 acc[8];
  float xsum[8];
  #pragma unroll
  for (int i = 0; i < 8; i++) {
    acc[i] = make_float4(0.f, 0.f, 0.f, 0.f);
    xsum[i] = 0.f;
  }
  int cg = tid & 15, rg = tid >> 4;
  const float4* x4 = (const float4*)x;
  for (int ch = 0; ch < 8; ch++) {
    __syncthreads();
    for (int s = tid; s < 512; s += 256) {
      int r = s >> 2, d4 = s & 3;
      int row = rowBase + r;
      float4 vv = make_float4(0.f, 0.f, 0.f, 0.f);
      if (row < n) vv = x4[row * 32 + (ch << 2) + d4];
      *(float4*)&Xs[r][d4 << 2] = vv;
    }
    __syncthreads();
    #pragma unroll
    for (int dq = 0; dq < 4; dq++) {
      int d0 = (ch << 4) + (dq << 2);
      float4 w0 = *(const float4*)&Ws[d0 + 0][cg << 2];
      float4 w1 = *(const float4*)&Ws[d0 + 1][cg << 2];
      float4 w2 = *(const float4*)&Ws[d0 + 2][cg << 2];
      float4 w3 = *(const float4*)&Ws[d0 + 3][cg << 2];
      #pragma unroll
      for (int i = 0; i < 8; i++) {
        float4 xv = *(const float4*)&Xs[(rg << 3) + i][dq << 2];
        xsum[i] += xv.x + xv.y + xv.z + xv.w;
        acc[i].x += xv.x * w0.x + xv.y * w1.x + xv.z * w2.x + xv.w * w3.x;
        acc[i].y += xv.x * w0.y + xv.y * w1.y + xv.z * w2.y + xv.w * w3.y;
        acc[i].z += xv.x * w0.z + xv.y * w1.z + xv.z * w2.z + xv.w * w3.z;
        acc[i].w += xv.x * w0.w + xv.y * w1.w + xv.z * w2.w + xv.w * w3.w;
      }
    }
  }
  int k = cg >> 2;
  int f = (cg & 3) << 2;
  #pragma unroll
  for (int i = 0; i < 8; i++) {
    int r = rowBase + (rg << 3) + i;
    if (r < n) {
      float sc = 1.0f / fmaxf(xsum[i], 1e-8f);
      float4 o = make_float4(acc[i].x * sc, acc[i].y * sc, acc[i].z * sc, acc[i].w * sc);
      *(float4*)&y[(k * n + r) * 16 + f] = o;
    }
  }
}

// ---------------- GEMM2: out[n][64] = sum_k G[k][n][:] @ W2[k] + b2 ----------------
__global__ __launch_bounds__(256) void k_gemm2(
    const float* __restrict__ G, const float* __restrict__ W2,
    const float* __restrict__ b2, float* __restrict__ out, int n) {
  __shared__ float Ws[64][64];
  __shared__ float Gs[128][36];
  int tid = threadIdx.x;
  int rowBase = blockIdx.x * 128;
  for (int s = tid; s < 4096; s += 256) ((float*)Ws)[s] = W2[s];
  float4 acc[8];
  #pragma unroll
  for (int i = 0; i < 8; i++) acc[i] = make_float4(0.f, 0.f, 0.f, 0.f);
  int cg = tid & 15, rg = tid >> 4;
  for (int ch = 0; ch < 2; ch++) {
    __syncthreads();
    for (int s = tid; s < 1024; s += 256) {
      int kk = s >> 9, rem = s & 511;
      int r = rem >> 2, f4 = rem & 3;
      int row = rowBase + r;
      float4 vv = make_float4(0.f, 0.f, 0.f, 0.f);
      if (row < n) vv = *(const float4*)&G[(((ch << 1) | kk) * n + row) * 16 + (f4 << 2)];
      *(float4*)&Gs[r][(kk << 4) | (f4 << 2)] = vv;
    }
    __syncthreads();
    #pragma unroll
    for (int dq = 0; dq < 8; dq++) {
      int d0 = (ch << 5) + (dq << 2);
      float4 w0 = *(const float4*)&Ws[d0 + 0][cg << 2];
      float4 w1 = *(const float4*)&Ws[d0 + 1][cg << 2];
      float4 w2 = *(const float4*)&Ws[d0 + 2][cg << 2];
      float4 w3 = *(const float4*)&Ws[d0 + 3][cg << 2];
      #pragma unroll
      for (int i = 0; i < 8; i++) {
        float4 gv = *(const float4*)&Gs[(rg << 3) + i][dq << 2];
        acc[i].x += gv.x * w0.x + gv.y * w1.x + gv.z * w2.x + gv.w * w3.x;
        acc[i].y += gv.x * w0.y + gv.y * w1.y + gv.z * w2.y + gv.w * w3.y;
        acc[i].z += gv.x * w0.z + gv.y * w1.z + gv.z * w2.z + gv.w * w3.z;
        acc[i].w += gv.x * w0.w + gv.y * w1.w + gv.z * w2.w + gv.w * w3.w;
      }
    }
  }
  float4 bb = *(const float4*)&b2[cg << 2];
  #pragma unroll
  for (int i = 0; i < 8; i++) {
    int r = rowBase + (rg << 3) + i;
    if (r < n) {
      *(float4*)&out[r * 64 + (cg << 2)] = make_float4(
          acc[i].x + bb.x, acc[i].y + bb.y, acc[i].z + bb.z, acc[i].w + bb.w);
    }
  }
}

// ---------------- launch ----------------
extern "C" void kernel_launch(void* const* d_in, const int* in_sizes, int n_in,
                              void* d_out, int out_size) {
  (void)n_in; (void)out_size;
  const float* x  = (const float*)d_in[0];
  const int*   ei = (const int*)d_in[1];
  const float* W1 = (const float*)d_in[2];
  const float* b1 = (const float*)d_in[3];
  const float* W2 = (const float*)d_in[4];
  const float* b2 = (const float*)d_in[5];
  float* out = (float*)d_out;
  int n = in_sizes[0] / 128;
  int E = in_sizes[1] / 2;

  int *cnt, *rp, *ofs, *bsum, *csr;
  float *dinv, *y, *t, *u, *G;
  cudaGetSymbolAddress((void**)&cnt,  g_cnt);
  cudaGetSymbolAddress((void**)&rp,   g_rp);
  cudaGetSymbolAddress((void**)&ofs,  g_ofs);
  cudaGetSymbolAddress((void**)&bsum, g_bsum);
  cudaGetSymbolAddress((void**)&dinv, g_dinv);
  cudaGetSymbolAddress((void**)&csr,  g_csr);
  cudaGetSymbolAddress((void**)&y,    g_y);
  cudaGetSymbolAddress((void**)&t,    g_t);
  cudaGetSymbolAddress((void**)&u,    g_u);
  cudaGetSymbolAddress((void**)&G,    g_G);

  const int TB = 256;
  int gN  = (n + TB - 1) / TB;
  int gE  = (E + TB - 1) / TB;
  int gR4 = (n * 4 + TB - 1) / TB;
  int gG  = (n + 127) / 128;
  int nb  = (n + 1023) / 1024;

  // CSR build (counting sort by dst); degree hist doubles as gcn_norm degree
  k_zero1<<<gN, TB>>>(cnt, n);
  k_hist<<<gE, TB>>>(ei, cnt, E);
  k_scan1<<<nb, 1024>>>(cnt, rp, bsum, dinv, ofs, n);
  k_scan2<<<1, 64>>>(bsum, nb);
  k_fill<<<gE, TB>>>(ei, rp, bsum, ofs, csr, E);

  // layer-1 projections (row-normalize fused)
  k_gemm1<<<gG, 256>>>(x, W1, y, n);

  // layer-1 Horner: G0 = relu(y0 + A(y1 + A(y2 + A*y3)) + b1)
  k_spmm<<<gR4, TB>>>(rp, cnt, bsum, csr, dinv, (const float4*)(y + 3 * n * 16),
                      (const float4*)(y + 2 * n * 16), nullptr, (float4*)t, n);
  k_spmm<<<gR4, TB>>>(rp, cnt, bsum, csr, dinv, (const float4*)t,
                      (const float4*)(y + 1 * n * 16), nullptr, (float4*)u, n);
  k_spmm<<<gR4, TB>>>(rp, cnt, bsum, csr, dinv, (const float4*)u,
                      (const float4*)y, b1, (float4*)G, n);

  // layer-2 hops: G[k+1] = A * G[k]
  for (int k = 0; k < 3; k++) {
    k_spmm<<<gR4, TB>>>(rp, cnt, bsum, csr, dinv, (const float4*)(G + k * n * 16),
                        nullptr, nullptr, (float4*)(G + (k + 1) * n * 16), n);
  }

  // combine + bias
  k_gemm2<<<gG, 256>>>(G, W2, b2, out, n);
}

// round 4
// speedup vs baseline: 1.2817x; 1.2817x over previous
#include <cuda_runtime.h>
#include <math.h>

#define NMAX 50000
#define EMAX 800000

// ---------------- scratch (no allocation allowed) ----------------
__device__ __align__(16) int   g_cnt[NMAX];        // in-degree (counting-sort hist)
__device__ __align__(16) int   g_rp[NMAX];         // CSR row ptr (FINAL, block-atomic base)
__device__ __align__(16) int   g_ofs[NMAX];        // fill cursors
__device__ int                 g_base;             // global edge counter for block bases
__device__ __align__(16) float g_dinv[NMAX];
__device__ __align__(16) float2 g_csr[EMAX];       // (src bits, weight)
__device__ __align__(16) float g_y[4 * NMAX * 16]; // layer-1 projections y_k
__device__ __align__(16) float g_t[NMAX * 16];
__device__ __align__(16) float g_u[NMAX * 16];
__device__ __align__(16) float g_G[4 * NMAX * 16]; // layer-2 hops

// ---------------- CSR build ----------------
__global__ void k_zero1(int* __restrict__ a, int* __restrict__ base, int n) {
  int i = blockIdx.x * blockDim.x + threadIdx.x;
  if (i < n) a[i] = 0;
  if (i == 0) *base = 0;
}

__global__ void k_hist(const int* __restrict__ ei, int* __restrict__ cnt, int E) {
  int e = blockIdx.x * blockDim.x + threadIdx.x;
  if (e < E) atomicAdd(&cnt[ei[E + e]], 1);
}

// per-1024-block exclusive scan (warp shuffles) + atomic block base -> FINAL rp.
// Also emits dinv and zeroes ofs. Block ordering in csr space is irrelevant:
// rows only need disjoint, correctly-sized ranges.
__global__ __launch_bounds__(1024) void k_scan1(const int* __restrict__ cnt,
                                                int* __restrict__ rp,
                                                int* __restrict__ base,
                                                float* __restrict__ dinv,
                                                int* __restrict__ ofs, int n) {
  __shared__ int ws[32];
  __shared__ int blockBase;
  int t = threadIdx.x;
  int i = blockIdx.x * 1024 + t;
  int c = (i < n) ? cnt[i] : 0;
  if (i < n) {
    dinv[i] = (c > 0) ? rsqrtf((float)c) : 0.f;
    ofs[i] = 0;
  }
  int s = c;
  #pragma unroll
  for (int o = 1; o < 32; o <<= 1) {
    int p = __shfl_up_sync(0xffffffffu, s, o);
    if ((t & 31) >= o) s += p;
  }
  if ((t & 31) == 31) ws[t >> 5] = s;
  __syncthreads();
  if (t < 32) {
    int b = ws[t];
    int sb = b;
    #pragma unroll
    for (int o = 1; o < 32; o <<= 1) {
      int p = __shfl_up_sync(0xffffffffu, sb, o);
      if (t >= o) sb += p;
    }
    ws[t] = sb - b;               // exclusive warp offset
    if (t == 31) blockBase = atomicAdd(base, sb);  // claim this block's range
  }
  __syncthreads();
  if (i < n) rp[i] = blockBase + (s - c) + ws[t >> 5];
}

// fill CSR entries: (src, dinv[src]*dinv[dst]) into dst buckets
__global__ void k_fill(const int* __restrict__ ei, const float* __restrict__ dinv,
                       const int* __restrict__ rp, int* __restrict__ ofs,
                       float2* __restrict__ csr, int E) {
  int e = blockIdx.x * blockDim.x + threadIdx.x;
  if (e >= E) return;
  int s = ei[e];
  int d = ei[E + e];
  int p = __ldg(&rp[d]) + atomicAdd(&ofs[d], 1);
  csr[p] = make_float2(__int_as_float(s), dinv[s] * dinv[d]);
}

// ---------------- gather SpMM: out[r] = epi(init[r] + sum_e w_e * in[src_e]) ----------------
// 4 threads per row (one float4 quad each), 4-way unrolled edge loop.
__global__ __launch_bounds__(256) void k_spmm(
    const int* __restrict__ rp, const int* __restrict__ cnt,
    const float2* __restrict__ csr, const float4* __restrict__ in,
    const float4* __restrict__ init, const float* __restrict__ bias,
    float4* __restrict__ out, int n) {
  int idx = blockIdx.x * blockDim.x + threadIdx.x;
  int r = idx >> 2;
  if (r >= n) return;
  int q = idx & 3;
  int start = __ldg(&rp[r]);
  int len = __ldg(&cnt[r]);
  float4 a0 = make_float4(0.f, 0.f, 0.f, 0.f);
  float4 a1 = make_float4(0.f, 0.f, 0.f, 0.f);
  if (init) a0 = init[(r << 2) + q];
  int i = 0;
  for (; i + 4 <= len; i += 4) {
    float2 e0 = __ldg(&csr[start + i + 0]);
    float2 e1 = __ldg(&csr[start + i + 1]);
    float2 e2 = __ldg(&csr[start + i + 2]);
    float2 e3 = __ldg(&csr[start + i + 3]);
    float4 v0 = __ldg(&in[(__float_as_int(e0.x) << 2) + q]);
    float4 v1 = __ldg(&in[(__float_as_int(e1.x) << 2) + q]);
    float4 v2 = __ldg(&in[(__float_as_int(e2.x) << 2) + q]);
    float4 v3 = __ldg(&in[(__float_as_int(e3.x) << 2) + q]);
    a0.x += e0.y * v0.x; a0.y += e0.y * v0.y; a0.z += e0.y * v0.z; a0.w += e0.y * v0.w;
    a1.x += e1.y * v1.x; a1.y += e1.y * v1.y; a1.z += e1.y * v1.z; a1.w += e1.y * v1.w;
    a0.x += e2.y * v2.x; a0.y += e2.y * v2.y; a0.z += e2.y * v2.z; a0.w += e2.y * v2.w;
    a1.x += e3.y * v3.x; a1.y += e3.y * v3.y; a1.z += e3.y * v3.z; a1.w += e3.y * v3.w;
  }
  for (; i < len; i++) {
    float2 e0 = __ldg(&csr[start + i]);
    float4 v0 = __ldg(&in[(__float_as_int(e0.x) << 2) + q]);
    a0.x += e0.y * v0.x; a0.y += e0.y * v0.y; a0.z += e0.y * v0.z; a0.w += e0.y * v0.w;
  }
  float4 acc = make_float4(a0.x + a1.x, a0.y + a1.y, a0.z + a1.z, a0.w + a1.w);
  if (bias) {
    float4 bb = ((const float4*)bias)[q];
    acc = make_float4(fmaxf(acc.x + bb.x, 0.f), fmaxf(acc.y + bb.y, 0.f),
                      fmaxf(acc.z + bb.z, 0.f), fmaxf(acc.w + bb.w, 0.f));
  }
  out[(r << 2) + q] = acc;
}

// ---------------- GEMM1: y[k][n][16] = (x/rowsum) @ W1[k], rowsum fused ----------------
__global__ __launch_bounds__(256) void k_gemm1(
    const float* __restrict__ x, const float* __restrict__ W1,
    float* __restrict__ y, int n) {
  __shared__ float Ws[128][64];
  __shared__ float Xs[128][16];
  int tid = threadIdx.x;
  int rowBase = blockIdx.x * 128;
  for (int s = tid; s < 8192; s += 256) {
    int d = s >> 6, c = s & 63;
    Ws[d][c] = W1[(((c >> 4) << 7) | d) * 16 + (c & 15)];
  }
  float4 acc[8];
  float xsum[8];
  #pragma unroll
  for (int i = 0; i < 8; i++) {
    acc[i] = make_float4(0.f, 0.f, 0.f, 0.f);
    xsum[i] = 0.f;
  }
  int cg = tid & 15, rg = tid >> 4;
  const float4* x4 = (const float4*)x;
  for (int ch = 0; ch < 8; ch++) {
    __syncthreads();
    for (int s = tid; s < 512; s += 256) {
      int r = s >> 2, d4 = s & 3;
      int row = rowBase + r;
      float4 vv = make_float4(0.f, 0.f, 0.f, 0.f);
      if (row < n) vv = x4[row * 32 + (ch << 2) + d4];
      *(float4*)&Xs[r][d4 << 2] = vv;
    }
    __syncthreads();
    #pragma unroll
    for (int dq = 0; dq < 4; dq++) {
      int d0 = (ch << 4) + (dq << 2);
      float4 w0 = *(const float4*)&Ws[d0 + 0][cg << 2];
      float4 w1 = *(const float4*)&Ws[d0 + 1][cg << 2];
      float4 w2 = *(const float4*)&Ws[d0 + 2][cg << 2];
      float4 w3 = *(const float4*)&Ws[d0 + 3][cg << 2];
      #pragma unroll
      for (int i = 0; i < 8; i++) {
        float4 xv = *(const float4*)&Xs[(rg << 3) + i][dq << 2];
        xsum[i] += xv.x + xv.y + xv.z + xv.w;
        acc[i].x += xv.x * w0.x + xv.y * w1.x + xv.z * w2.x + xv.w * w3.x;
        acc[i].y += xv.x * w0.y + xv.y * w1.y + xv.z * w2.y + xv.w * w3.y;
        acc[i].z += xv.x * w0.z + xv.y * w1.z + xv.z * w2.z + xv.w * w3.z;
        acc[i].w += xv.x * w0.w + xv.y * w1.w + xv.z * w2.w + xv.w * w3.w;
      }
    }
  }
  int k = cg >> 2;
  int f = (cg & 3) << 2;
  #pragma unroll
  for (int i = 0; i < 8; i++) {
    int r = rowBase + (rg << 3) + i;
    if (r < n) {
      float sc = 1.0f / fmaxf(xsum[i], 1e-8f);
      float4 o = make_float4(acc[i].x * sc, acc[i].y * sc, acc[i].z * sc, acc[i].w * sc);
      *(float4*)&y[(k * n + r) * 16 + f] = o;
    }
  }
}

// ---------------- GEMM2: out[n][64] = sum_k G[k][n][:] @ W2[k] + b2 ----------------
__global__ __launch_bounds__(256) void k_gemm2(
    const float* __restrict__ G, const float* __restrict__ W2,
    const float* __restrict__ b2, float* __restrict__ out, int n) {
  __shared__ float Ws[64][64];
  __shared__ float Gs[128][36];
  int tid = threadIdx.x;
  int rowBase = blockIdx.x * 128;
  for (int s = tid; s < 4096; s += 256) ((float*)Ws)[s] = W2[s];
  float4 acc[8];
  #pragma unroll
  for (int i = 0; i < 8; i++) acc[i] = make_float4(0.f, 0.f, 0.f, 0.f);
  int cg = tid & 15, rg = tid >> 4;
  for (int ch = 0; ch < 2; ch++) {
    __syncthreads();
    for (int s = tid; s < 1024; s += 256) {
      int kk = s >> 9, rem = s & 511;
      int r = rem >> 2, f4 = rem & 3;
      int row = rowBase + r;
      float4 vv = make_float4(0.f, 0.f, 0.f, 0.f);
      if (row < n) vv = *(const float4*)&G[(((ch << 1) | kk) * n + row) * 16 + (f4 << 2)];
      *(float4*)&Gs[r][(kk << 4) | (f4 << 2)] = vv;
    }
    __syncthreads();
    #pragma unroll
    for (int dq = 0; dq < 8; dq++) {
      int d0 = (ch << 5) + (dq << 2);
      float4 w0 = *(const float4*)&Ws[d0 + 0][cg << 2];
      float4 w1 = *(const float4*)&Ws[d0 + 1][cg << 2];
      float4 w2 = *(const float4*)&Ws[d0 + 2][cg << 2];
      float4 w3 = *(const float4*)&Ws[d0 + 3][cg << 2];
      #pragma unroll
      for (int i = 0; i < 8; i++) {
        float4 gv = *(const float4*)&Gs[(rg << 3) + i][dq << 2];
        acc[i].x += gv.x * w0.x + gv.y * w1.x + gv.z * w2.x + gv.w * w3.x;
        acc[i].y += gv.x * w0.y + gv.y * w1.y + gv.z * w2.y + gv.w * w3.y;
        acc[i].z += gv.x * w0.z + gv.y * w1.z + gv.z * w2.z + gv.w * w3.z;
        acc[i].w += gv.x * w0.w + gv.y * w1.w + gv.z * w2.w + gv.w * w3.w;
      }
    }
  }
  float4 bb = *(const float4*)&b2[cg << 2];
  #pragma unroll
  for (int i = 0; i < 8; i++) {
    int r = rowBase + (rg << 3) + i;
    if (r < n) {
      *(float4*)&out[r * 64 + (cg << 2)] = make_float4(
          acc[i].x + bb.x, acc[i].y + bb.y, acc[i].z + bb.z, acc[i].w + bb.w);
    }
  }
}

// ---------------- launch ----------------
extern "C" void kernel_launch(void* const* d_in, const int* in_sizes, int n_in,
                              void* d_out, int out_size) {
  (void)n_in; (void)out_size;
  const float* x  = (const float*)d_in[0];
  const int*   ei = (const int*)d_in[1];
  const float* W1 = (const float*)d_in[2];
  const float* b1 = (const float*)d_in[3];
  const float* W2 = (const float*)d_in[4];
  const float* b2 = (const float*)d_in[5];
  float* out = (float*)d_out;
  int n = in_sizes[0] / 128;
  int E = in_sizes[1] / 2;

  int *cnt, *rp, *ofs, *base;
  float *dinv, *y, *t, *u, *G;
  float2* csr;
  cudaGetSymbolAddress((void**)&cnt,  g_cnt);
  cudaGetSymbolAddress((void**)&rp,   g_rp);
  cudaGetSymbolAddress((void**)&ofs,  g_ofs);
  cudaGetSymbolAddress((void**)&base, g_base);
  cudaGetSymbolAddress((void**)&dinv, g_dinv);
  cudaGetSymbolAddress((void**)&csr,  g_csr);
  cudaGetSymbolAddress((void**)&y,    g_y);
  cudaGetSymbolAddress((void**)&t,    g_t);
  cudaGetSymbolAddress((void**)&u,    g_u);
  cudaGetSymbolAddress((void**)&G,    g_G);

  const int TB = 256;
  int gN  = (n + TB - 1) / TB;
  int gE  = (E + TB - 1) / TB;
  int gR4 = (n * 4 + TB - 1) / TB;
  int gG  = (n + 127) / 128;
  int nb  = (n + 1023) / 1024;

  // CSR build (counting sort by dst); degree hist doubles as gcn_norm degree
  k_zero1<<<gN, TB>>>(cnt, base, n);
  k_hist<<<gE, TB>>>(ei, cnt, E);
  k_scan1<<<nb, 1024>>>(cnt, rp, base, dinv, ofs, n);
  k_fill<<<gE, TB>>>(ei, dinv, rp, ofs, csr, E);

  // layer-1 projections (row-normalize fused)
  k_gemm1<<<gG, 256>>>(x, W1, y, n);

  // layer-1 Horner: G0 = relu(y0 + A(y1 + A(y2 + A*y3)) + b1)
  k_spmm<<<gR4, TB>>>(rp, cnt, csr, (const float4*)(y + 3 * n * 16),
                      (const float4*)(y + 2 * n * 16), nullptr, (float4*)t, n);
  k_spmm<<<gR4, TB>>>(rp, cnt, csr, (const float4*)t,
                      (const float4*)(y + 1 * n * 16), nullptr, (float4*)u, n);
  k_spmm<<<gR4, TB>>>(rp, cnt, csr, (const float4*)u,
                      (const float4*)y, b1, (float4*)G, n);

  // layer-2 hops: G[k+1] = A * G[k]
  for (int k = 0; k < 3; k++) {
    k_spmm<<<gR4, TB>>>(rp, cnt, csr, (const float4*)(G + k * n * 16),
                        nullptr, nullptr, (float4*)(G + (k + 1) * n * 16), n);
  }

  // combine + bias
  k_gemm2<<<gG, 256>>>(G, W2, b2, out, n);
}

// round 5
// speedup vs baseline: 1.2891x; 1.0058x over previous
#include <cuda_runtime.h>
#include <math.h>

#define NMAX 50000
#define EMAX 800000

// ---------------- scratch (no allocation allowed) ----------------
__device__ __align__(16) int   g_cnt[NMAX];        // in-degree (counting-sort hist)
__device__ __align__(16) int   g_rp[NMAX];         // CSR row ptr; fill advances it to row END
__device__ int                 g_base;             // global edge counter for block bases
__device__ __align__(16) float g_dinv[NMAX];
__device__ __align__(16) float2 g_csr[EMAX];       // (src bits, weight)
__device__ __align__(16) float g_y[4 * NMAX * 16]; // layer-1 projections y_k
__device__ __align__(16) float g_t[NMAX * 16];
__device__ __align__(16) float g_u[NMAX * 16];
__device__ __align__(16) float g_G[4 * NMAX * 16]; // layer-2 hops

// ---------------- CSR build ----------------
__global__ void k_zero1(int* __restrict__ a, int* __restrict__ base, int n) {
  int i = blockIdx.x * blockDim.x + threadIdx.x;
  if (i < n) a[i] = 0;
  if (i == 0) *base = 0;
}

__global__ void k_hist(const int* __restrict__ ei, int* __restrict__ cnt, int E) {
  int e = blockIdx.x * blockDim.x + threadIdx.x;
  if (e < E) atomicAdd(&cnt[ei[E + e]], 1);
}

// per-1024-block exclusive scan (warp shuffles) + atomic block base -> FINAL rp.
// Also emits dinv. Block ordering in csr space is irrelevant: rows only need
// disjoint, correctly-sized ranges.
__global__ __launch_bounds__(1024) void k_scan1(const int* __restrict__ cnt,
                                                int* __restrict__ rp,
                                                int* __restrict__ base,
                                                float* __restrict__ dinv, int n) {
  __shared__ int ws[32];
  __shared__ int blockBase;
  int t = threadIdx.x;
  int i = blockIdx.x * 1024 + t;
  int c = (i < n) ? cnt[i] : 0;
  if (i < n) dinv[i] = (c > 0) ? rsqrtf((float)c) : 0.f;
  int s = c;
  #pragma unroll
  for (int o = 1; o < 32; o <<= 1) {
    int p = __shfl_up_sync(0xffffffffu, s, o);
    if ((t & 31) >= o) s += p;
  }
  if ((t & 31) == 31) ws[t >> 5] = s;
  __syncthreads();
  if (t < 32) {
    int b = ws[t];
    int sb = b;
    #pragma unroll
    for (int o = 1; o < 32; o <<= 1) {
      int p = __shfl_up_sync(0xffffffffu, sb, o);
      if (t >= o) sb += p;
    }
    ws[t] = sb - b;               // exclusive warp offset
    if (t == 31) blockBase = atomicAdd(base, sb);  // claim this block's range
  }
  __syncthreads();
  if (i < n) rp[i] = blockBase + (s - c) + ws[t >> 5];
}

// fill CSR entries: (src, dinv[src]*dinv[dst]) into dst buckets.
// rp doubles as the fill cursor; after this kernel rp[d] = end of row d.
// 2 edges per thread for latency-chain overlap.
__global__ void k_fill(const int* __restrict__ ei, const float* __restrict__ dinv,
                       int* __restrict__ rp, float2* __restrict__ csr, int E) {
  int e = (blockIdx.x * blockDim.x + threadIdx.x) * 2;
  if (e >= E) return;
  int s0 = ei[e];
  int d0 = ei[E + e];
  float w0 = dinv[s0] * dinv[d0];
  int p0 = atomicAdd(&rp[d0], 1);
  if (e + 1 < E) {
    int s1 = ei[e + 1];
    int d1 = ei[E + e + 1];
    float w1 = dinv[s1] * dinv[d1];
    int p1 = atomicAdd(&rp[d1], 1);
    csr[p0] = make_float2(__int_as_float(s0), w0);
    csr[p1] = make_float2(__int_as_float(s1), w1);
  } else {
    csr[p0] = make_float2(__int_as_float(s0), w0);
  }
}

// ---------------- gather SpMM: out[r] = epi(init[r] + sum_e w_e * in[src_e]) ----------------
// rp[r] is the row END (post-fill); start = rp[r] - cnt[r].
// 4 threads per row (one float4 quad each), 8-wide unrolled edge loop.
__global__ __launch_bounds__(256) void k_spmm(
    const int* __restrict__ rp, const int* __restrict__ cnt,
    const float2* __restrict__ csr, const float4* __restrict__ in,
    const float4* __restrict__ init, const float* __restrict__ bias,
    float4* __restrict__ out, int n) {
  int idx = blockIdx.x * blockDim.x + threadIdx.x;
  int r = idx >> 2;
  if (r >= n) return;
  int q = idx & 3;
  int len = __ldg(&cnt[r]);
  int start = __ldg(&rp[r]) - len;
  float4 a0 = make_float4(0.f, 0.f, 0.f, 0.f);
  float4 a1 = make_float4(0.f, 0.f, 0.f, 0.f);
  if (init) a0 = init[(r << 2) + q];
  int i = 0;
  for (; i + 8 <= len; i += 8) {
    float2 e0 = __ldg(&csr[start + i + 0]);
    float2 e1 = __ldg(&csr[start + i + 1]);
    float2 e2 = __ldg(&csr[start + i + 2]);
    float2 e3 = __ldg(&csr[start + i + 3]);
    float2 e4 = __ldg(&csr[start + i + 4]);
    float2 e5 = __ldg(&csr[start + i + 5]);
    float2 e6 = __ldg(&csr[start + i + 6]);
    float2 e7 = __ldg(&csr[start + i + 7]);
    float4 v0 = __ldg(&in[(__float_as_int(e0.x) << 2) + q]);
    float4 v1 = __ldg(&in[(__float_as_int(e1.x) << 2) + q]);
    float4 v2 = __ldg(&in[(__float_as_int(e2.x) << 2) + q]);
    float4 v3 = __ldg(&in[(__float_as_int(e3.x) << 2) + q]);
    float4 v4 = __ldg(&in[(__float_as_int(e4.x) << 2) + q]);
    float4 v5 = __ldg(&in[(__float_as_int(e5.x) << 2) + q]);
    float4 v6 = __ldg(&in[(__float_as_int(e6.x) << 2) + q]);
    float4 v7 = __ldg(&in[(__float_as_int(e7.x) << 2) + q]);
    a0.x += e0.y * v0.x; a0.y += e0.y * v0.y; a0.z += e0.y * v0.z; a0.w += e0.y * v0.w;
    a1.x += e1.y * v1.x; a1.y += e1.y * v1.y; a1.z += e1.y * v1.z; a1.w += e1.y * v1.w;
    a0.x += e2.y * v2.x; a0.y += e2.y * v2.y; a0.z += e2.y * v2.z; a0.w += e2.y * v2.w;
    a1.x += e3.y * v3.x; a1.y += e3.y * v3.y; a1.z += e3.y * v3.z; a1.w += e3.y * v3.w;
    a0.x += e4.y * v4.x; a0.y += e4.y * v4.y; a0.z += e4.y * v4.z; a0.w += e4.y * v4.w;
    a1.x += e5.y * v5.x; a1.y += e5.y * v5.y; a1.z += e5.y * v5.z; a1.w += e5.y * v5.w;
    a0.x += e6.y * v6.x; a0.y += e6.y * v6.y; a0.z += e6.y * v6.z; a0.w += e6.y * v6.w;
    a1.x += e7.y * v7.x; a1.y += e7.y * v7.y; a1.z += e7.y * v7.z; a1.w += e7.y * v7.w;
  }
  for (; i + 4 <= len; i += 4) {
    float2 e0 = __ldg(&csr[start + i + 0]);
    float2 e1 = __ldg(&csr[start + i + 1]);
    float2 e2 = __ldg(&csr[start + i + 2]);
    float2 e3 = __ldg(&csr[start + i + 3]);
    float4 v0 = __ldg(&in[(__float_as_int(e0.x) << 2) + q]);
    float4 v1 = __ldg(&in[(__float_as_int(e1.x) << 2) + q]);
    float4 v2 = __ldg(&in[(__float_as_int(e2.x) << 2) + q]);
    float4 v3 = __ldg(&in[(__float_as_int(e3.x) << 2) + q]);
    a0.x += e0.y * v0.x; a0.y += e0.y * v0.y; a0.z += e0.y * v0.z; a0.w += e0.y * v0.w;
    a1.x += e1.y * v1.x; a1.y += e1.y * v1.y; a1.z += e1.y * v1.z; a1.w += e1.y * v1.w;
    a0.x += e2.y * v2.x; a0.y += e2.y * v2.y; a0.z += e2.y * v2.z; a0.w += e2.y * v2.w;
    a1.x += e3.y * v3.x; a1.y += e3.y * v3.y; a1.z += e3.y * v3.z; a1.w += e3.y * v3.w;
  }
  for (; i < len; i++) {
    float2 e0 = __ldg(&csr[start + i]);
    float4 v0 = __ldg(&in[(__float_as_int(e0.x) << 2) + q]);
    a0.x += e0.y * v0.x; a0.y += e0.y * v0.y; a0.z += e0.y * v0.z; a0.w += e0.y * v0.w;
  }
  float4 acc = make_float4(a0.x + a1.x, a0.y + a1.y, a0.z + a1.z, a0.w + a1.w);
  if (bias) {
    float4 bb = ((const float4*)bias)[q];
    acc = make_float4(fmaxf(acc.x + bb.x, 0.f), fmaxf(acc.y + bb.y, 0.f),
                      fmaxf(acc.z + bb.z, 0.f), fmaxf(acc.w + bb.w, 0.f));
  }
  out[(r << 2) + q] = acc;
}

// ---------------- GEMM1: y[k][n][16] = (x/rowsum) @ W1[k], rowsum fused ----------------
__global__ __launch_bounds__(256) void k_gemm1(
    const float* __restrict__ x, const float* __restrict__ W1,
    float* __restrict__ y, int n) {
  __shared__ float Ws[128][64];
  __shared__ float Xs[128][16];
  int tid = threadIdx.x;
  int rowBase = blockIdx.x * 128;
  for (int s = tid; s < 8192; s += 256) {
    int d = s >> 6, c = s & 63;
    Ws[d][c] = W1[(((c >> 4) << 7) | d) * 16 + (c & 15)];
  }
  float4 acc[8];
  float xsum[8];
  #pragma unroll
  for (int i = 0; i < 8; i++) {
    acc[i] = make_float4(0.f, 0.f, 0.f, 0.f);
    xsum[i] = 0.f;
  }
  int cg = tid & 15, rg = tid >> 4;
  const float4* x4 = (const float4*)x;
  for (int ch = 0; ch < 8; ch++) {
    __syncthreads();
    for (int s = tid; s < 512; s += 256) {
      int r = s >> 2, d4 = s & 3;
      int row = rowBase + r;
      float4 vv = make_float4(0.f, 0.f, 0.f, 0.f);
      if (row < n) vv = x4[row * 32 + (ch << 2) + d4];
      *(float4*)&Xs[r][d4 << 2] = vv;
    }
    __syncthreads();
    #pragma unroll
    for (int dq = 0; dq < 4; dq++) {
      int d0 = (ch << 4) + (dq << 2);
      float4 w0 = *(const float4*)&Ws[d0 + 0][cg << 2];
      float4 w1 = *(const float4*)&Ws[d0 + 1][cg << 2];
      float4 w2 = *(const float4*)&Ws[d0 + 2][cg << 2];
      float4 w3 = *(const float4*)&Ws[d0 + 3][cg << 2];
      #pragma unroll
      for (int i = 0; i < 8; i++) {
        float4 xv = *(const float4*)&Xs[(rg << 3) + i][dq << 2];
        xsum[i] += xv.x + xv.y + xv.z + xv.w;
        acc[i].x += xv.x * w0.x + xv.y * w1.x + xv.z * w2.x + xv.w * w3.x;
        acc[i].y += xv.x * w0.y + xv.y * w1.y + xv.z * w2.y + xv.w * w3.y;
        acc[i].z += xv.x * w0.z + xv.y * w1.z + xv.z * w2.z + xv.w * w3.z;
        acc[i].w += xv.x * w0.w + xv.y * w1.w + xv.z * w2.w + xv.w * w3.w;
      }
    }
  }
  int k = cg >> 2;
  int f = (cg & 3) << 2;
  #pragma unroll
  for (int i = 0; i < 8; i++) {
    int r = rowBase + (rg << 3) + i;
    if (r < n) {
      float sc = 1.0f / fmaxf(xsum[i], 1e-8f);
      float4 o = make_float4(acc[i].x * sc, acc[i].y * sc, acc[i].z * sc, acc[i].w * sc);
      *(float4*)&y[(k * n + r) * 16 + f] = o;
    }
  }
}

// ---------------- GEMM2: out[n][64] = sum_k G[k][n][:] @ W2[k] + b2 ----------------
__global__ __launch_bounds__(256) void k_gemm2(
    const float* __restrict__ G, const float* __restrict__ W2,
    const float* __restrict__ b2, float* __restrict__ out, int n) {
  __shared__ float Ws[64][64];
  __shared__ float Gs[128][36];
  int tid = threadIdx.x;
  int rowBase = blockIdx.x * 128;
  for (int s = tid; s < 4096; s += 256) ((float*)Ws)[s] = W2[s];
  float4 acc[8];
  #pragma unroll
  for (int i = 0; i < 8; i++) acc[i] = make_float4(0.f, 0.f, 0.f, 0.f);
  int cg = tid & 15, rg = tid >> 4;
  for (int ch = 0; ch < 2; ch++) {
    __syncthreads();
    for (int s = tid; s < 1024; s += 256) {
      int kk = s >> 9, rem = s & 511;
      int r = rem >> 2, f4 = rem & 3;
      int row = rowBase + r;
      float4 vv = make_float4(0.f, 0.f, 0.f, 0.f);
      if (row < n) vv = *(const float4*)&G[(((ch << 1) | kk) * n + row) * 16 + (f4 << 2)];
      *(float4*)&Gs[r][(kk << 4) | (f4 << 2)] = vv;
    }
    __syncthreads();
    #pragma unroll
    for (int dq = 0; dq < 8; dq++) {
      int d0 = (ch << 5) + (dq << 2);
      float4 w0 = *(const float4*)&Ws[d0 + 0][cg << 2];
      float4 w1 = *(const float4*)&Ws[d0 + 1][cg << 2];
      float4 w2 = *(const float4*)&Ws[d0 + 2][cg << 2];
      float4 w3 = *(const float4*)&Ws[d0 + 3][cg << 2];
      #pragma unroll
      for (int i = 0; i < 8; i++) {
        float4 gv = *(const float4*)&Gs[(rg << 3) + i][dq << 2];
        acc[i].x += gv.x * w0.x + gv.y * w1.x + gv.z * w2.x + gv.w * w3.x;
        acc[i].y += gv.x * w0.y + gv.y * w1.y + gv.z * w2.y + gv.w * w3.y;
        acc[i].z += gv.x * w0.z + gv.y * w1.z + gv.z * w2.z + gv.w * w3.z;
        acc[i].w += gv.x * w0.w + gv.y * w1.w + gv.z * w2.w + gv.w * w3.w;
      }
    }
  }
  float4 bb = *(const float4*)&b2[cg << 2];
  #pragma unroll
  for (int i = 0; i < 8; i++) {
    int r = rowBase + (rg << 3) + i;
    if (r < n) {
      *(float4*)&out[r * 64 + (cg << 2)] = make_float4(
          acc[i].x + bb.x, acc[i].y + bb.y, acc[i].z + bb.z, acc[i].w + bb.w);
    }
  }
}

// ---------------- launch ----------------
extern "C" void kernel_launch(void* const* d_in, const int* in_sizes, int n_in,
                              void* d_out, int out_size) {
  (void)n_in; (void)out_size;
  const float* x  = (const float*)d_in[0];
  const int*   ei = (const int*)d_in[1];
  const float* W1 = (const float*)d_in[2];
  const float* b1 = (const float*)d_in[3];
  const float* W2 = (const float*)d_in[4];
  const float* b2 = (const float*)d_in[5];
  float* out = (float*)d_out;
  int n = in_sizes[0] / 128;
  int E = in_sizes[1] / 2;

  int *cnt, *rp, *base;
  float *dinv, *y, *t, *u, *G;
  float2* csr;
  cudaGetSymbolAddress((void**)&cnt,  g_cnt);
  cudaGetSymbolAddress((void**)&rp,   g_rp);
  cudaGetSymbolAddress((void**)&base, g_base);
  cudaGetSymbolAddress((void**)&dinv, g_dinv);
  cudaGetSymbolAddress((void**)&csr,  g_csr);
  cudaGetSymbolAddress((void**)&y,    g_y);
  cudaGetSymbolAddress((void**)&t,    g_t);
  cudaGetSymbolAddress((void**)&u,    g_u);
  cudaGetSymbolAddress((void**)&G,    g_G);

  const int TB = 256;
  int gN  = (n + TB - 1) / TB;
  int gE  = (E + TB - 1) / TB;
  int gE2 = (E / 2 + TB - 1) / TB;
  int gR4 = (n * 4 + TB - 1) / TB;
  int gG  = (n + 127) / 128;
  int nb  = (n + 1023) / 1024;

  // CSR build (counting sort by dst); degree hist doubles as gcn_norm degree
  k_zero1<<<gN, TB>>>(cnt, base, n);
  k_hist<<<gE, TB>>>(ei, cnt, E);
  k_scan1<<<nb, 1024>>>(cnt, rp, base, dinv, n);
  // launch #4 -> profiled: layer-1 projections (row-normalize fused)
  k_gemm1<<<gG, 256>>>(x, W1, y, n);
  k_fill<<<gE2, TB>>>(ei, dinv, rp, csr, E);

  // layer-1 Horner: G0 = relu(y0 + A(y1 + A(y2 + A*y3)) + b1)
  k_spmm<<<gR4, TB>>>(rp, cnt, csr, (const float4*)(y + 3 * n * 16),
                      (const float4*)(y + 2 * n * 16), nullptr, (float4*)t, n);
  k_spmm<<<gR4, TB>>>(rp, cnt, csr, (const float4*)t,
                      (const float4*)(y + 1 * n * 16), nullptr, (float4*)u, n);
  k_spmm<<<gR4, TB>>>(rp, cnt, csr, (const float4*)u,
                      (const float4*)y, b1, (float4*)G, n);

  // layer-2 hops: G[k+1] = A * G[k]
  for (int k = 0; k < 3; k++) {
    k_spmm<<<gR4, TB>>>(rp, cnt, csr, (const float4*)(G + k * n * 16),
                        nullptr, nullptr, (float4*)(G + (k + 1) * n * 16), n);
  }

  // combine + bias
  k_gemm2<<<gG, 256>>>(G, W2, b2, out, n);
}

// round 6
// speedup vs baseline: 1.2910x; 1.0015x over previous
#include <cuda_runtime.h>
#include <math.h>

#define NMAX 50000
#define EMAX 800000

// ---------------- scratch (no allocation allowed) ----------------
__device__ __align__(16) int   g_cnt[NMAX];        // in-degree (counting-sort hist)
__device__ __align__(16) int   g_rp[NMAX];         // CSR row ptr; fill advances it to row END
__device__ int                 g_base;             // global edge counter for block bases
__device__ __align__(16) float g_dinv[NMAX];
__device__ __align__(16) float g_invrs[NMAX];
__device__ __align__(16) float2 g_csr[EMAX];       // (src bits, weight)
__device__ __align__(16) float g_y[4 * NMAX * 16]; // layer-1 projections y_k
__device__ __align__(16) float g_t[NMAX * 16];
__device__ __align__(16) float g_u[NMAX * 16];
__device__ __align__(16) float g_G[4 * NMAX * 16]; // layer-2 hops

// ---------------- CSR build ----------------
__global__ void k_zero1(int* __restrict__ a, int* __restrict__ base, int n) {
  int i = blockIdx.x * blockDim.x + threadIdx.x;
  if (i < n) a[i] = 0;
  if (i == 0) *base = 0;
}

__global__ void k_hist(const int* __restrict__ ei, int* __restrict__ cnt, int E) {
  int e = blockIdx.x * blockDim.x + threadIdx.x;
  if (e < E) atomicAdd(&cnt[ei[E + e]], 1);
}

// warp per row: inv_rowsum = 1 / max(sum(x_row), 1e-8)
__global__ void k_invrs(const float* __restrict__ x, float* __restrict__ invrs, int n) {
  int w = (blockIdx.x * blockDim.x + threadIdx.x) >> 5;
  int lane = threadIdx.x & 31;
  if (w >= n) return;
  const float4* x4 = (const float4*)x;
  float4 v = x4[w * 32 + lane];
  float s = v.x + v.y + v.z + v.w;
  #pragma unroll
  for (int o = 16; o; o >>= 1) s += __shfl_xor_sync(0xffffffffu, s, o);
  if (lane == 0) invrs[w] = 1.0f / fmaxf(s, 1e-8f);
}

// per-1024-block exclusive scan (warp shuffles) + atomic block base -> FINAL rp.
// Also emits dinv. Block ordering in csr space is irrelevant.
__global__ __launch_bounds__(1024) void k_scan1(const int* __restrict__ cnt,
                                                int* __restrict__ rp,
                                                int* __restrict__ base,
                                                float* __restrict__ dinv, int n) {
  __shared__ int ws[32];
  __shared__ int blockBase;
  int t = threadIdx.x;
  int i = blockIdx.x * 1024 + t;
  int c = (i < n) ? cnt[i] : 0;
  if (i < n) dinv[i] = (c > 0) ? rsqrtf((float)c) : 0.f;
  int s = c;
  #pragma unroll
  for (int o = 1; o < 32; o <<= 1) {
    int p = __shfl_up_sync(0xffffffffu, s, o);
    if ((t & 31) >= o) s += p;
  }
  if ((t & 31) == 31) ws[t >> 5] = s;
  __syncthreads();
  if (t < 32) {
    int b = ws[t];
    int sb = b;
    #pragma unroll
    for (int o = 1; o < 32; o <<= 1) {
      int p = __shfl_up_sync(0xffffffffu, sb, o);
      if (t >= o) sb += p;
    }
    ws[t] = sb - b;
    if (t == 31) blockBase = atomicAdd(base, sb);
  }
  __syncthreads();
  if (i < n) rp[i] = blockBase + (s - c) + ws[t >> 5];
}

// fill CSR entries: (src, dinv[src]*dinv[dst]) into dst buckets.
// rp doubles as the fill cursor; after this kernel rp[d] = end of row d.
__global__ void k_fill(const int* __restrict__ ei, const float* __restrict__ dinv,
                       int* __restrict__ rp, float2* __restrict__ csr, int E) {
  int e = (blockIdx.x * blockDim.x + threadIdx.x) * 2;
  if (e >= E) return;
  int s0 = ei[e];
  int d0 = ei[E + e];
  float w0 = dinv[s0] * dinv[d0];
  int p0 = atomicAdd(&rp[d0], 1);
  if (e + 1 < E) {
    int s1 = ei[e + 1];
    int d1 = ei[E + e + 1];
    float w1 = dinv[s1] * dinv[d1];
    int p1 = atomicAdd(&rp[d1], 1);
    csr[p0] = make_float2(__int_as_float(s0), w0);
    csr[p1] = make_float2(__int_as_float(s1), w1);
  } else {
    csr[p0] = make_float2(__int_as_float(s0), w0);
  }
}

// ---------------- gather SpMM: out[r] = epi(init[r] + sum_e w_e * in[src_e]) ----------------
// rp[r] is the row END (post-fill); start = rp[r] - cnt[r].
__global__ __launch_bounds__(256) void k_spmm(
    const int* __restrict__ rp, const int* __restrict__ cnt,
    const float2* __restrict__ csr, const float4* __restrict__ in,
    const float4* __restrict__ init, const float* __restrict__ bias,
    float4* __restrict__ out, int n) {
  int idx = blockIdx.x * blockDim.x + threadIdx.x;
  int r = idx >> 2;
  if (r >= n) return;
  int q = idx & 3;
  int len = __ldg(&cnt[r]);
  int start = __ldg(&rp[r]) - len;
  float4 a0 = make_float4(0.f, 0.f, 0.f, 0.f);
  float4 a1 = make_float4(0.f, 0.f, 0.f, 0.f);
  if (init) a0 = init[(r << 2) + q];
  int i = 0;
  for (; i + 8 <= len; i += 8) {
    float2 e0 = __ldg(&csr[start + i + 0]);
    float2 e1 = __ldg(&csr[start + i + 1]);
    float2 e2 = __ldg(&csr[start + i + 2]);
    float2 e3 = __ldg(&csr[start + i + 3]);
    float2 e4 = __ldg(&csr[start + i + 4]);
    float2 e5 = __ldg(&csr[start + i + 5]);
    float2 e6 = __ldg(&csr[start + i + 6]);
    float2 e7 = __ldg(&csr[start + i + 7]);
    float4 v0 = __ldg(&in[(__float_as_int(e0.x) << 2) + q]);
    float4 v1 = __ldg(&in[(__float_as_int(e1.x) << 2) + q]);
    float4 v2 = __ldg(&in[(__float_as_int(e2.x) << 2) + q]);
    float4 v3 = __ldg(&in[(__float_as_int(e3.x) << 2) + q]);
    float4 v4 = __ldg(&in[(__float_as_int(e4.x) << 2) + q]);
    float4 v5 = __ldg(&in[(__float_as_int(e5.x) << 2) + q]);
    float4 v6 = __ldg(&in[(__float_as_int(e6.x) << 2) + q]);
    float4 v7 = __ldg(&in[(__float_as_int(e7.x) << 2) + q]);
    a0.x += e0.y * v0.x; a0.y += e0.y * v0.y; a0.z += e0.y * v0.z; a0.w += e0.y * v0.w;
    a1.x += e1.y * v1.x; a1.y += e1.y * v1.y; a1.z += e1.y * v1.z; a1.w += e1.y * v1.w;
    a0.x += e2.y * v2.x; a0.y += e2.y * v2.y; a0.z += e2.y * v2.z; a0.w += e2.y * v2.w;
    a1.x += e3.y * v3.x; a1.y += e3.y * v3.y; a1.z += e3.y * v3.z; a1.w += e3.y * v3.w;
    a0.x += e4.y * v4.x; a0.y += e4.y * v4.y; a0.z += e4.y * v4.z; a0.w += e4.y * v4.w;
    a1.x += e5.y * v5.x; a1.y += e5.y * v5.y; a1.z += e5.y * v5.z; a1.w += e5.y * v5.w;
    a0.x += e6.y * v6.x; a0.y += e6.y * v6.y; a0.z += e6.y * v6.z; a0.w += e6.y * v6.w;
    a1.x += e7.y * v7.x; a1.y += e7.y * v7.y; a1.z += e7.y * v7.z; a1.w += e7.y * v7.w;
  }
  for (; i + 4 <= len; i += 4) {
    float2 e0 = __ldg(&csr[start + i + 0]);
    float2 e1 = __ldg(&csr[start + i + 1]);
    float2 e2 = __ldg(&csr[start + i + 2]);
    float2 e3 = __ldg(&csr[start + i + 3]);
    float4 v0 = __ldg(&in[(__float_as_int(e0.x) << 2) + q]);
    float4 v1 = __ldg(&in[(__float_as_int(e1.x) << 2) + q]);
    float4 v2 = __ldg(&in[(__float_as_int(e2.x) << 2) + q]);
    float4 v3 = __ldg(&in[(__float_as_int(e3.x) << 2) + q]);
    a0.x += e0.y * v0.x; a0.y += e0.y * v0.y; a0.z += e0.y * v0.z; a0.w += e0.y * v0.w;
    a1.x += e1.y * v1.x; a1.y += e1.y * v1.y; a1.z += e1.y * v1.z; a1.w += e1.y * v1.w;
    a0.x += e2.y * v2.x; a0.y += e2.y * v2.y; a0.z += e2.y * v2.z; a0.w += e2.y * v2.w;
    a1.x += e3.y * v3.x; a1.y += e3.y * v3.y; a1.z += e3.y * v3.z; a1.w += e3.y * v3.w;
  }
  for (; i < len; i++) {
    float2 e0 = __ldg(&csr[start + i]);
    float4 v0 = __ldg(&in[(__float_as_int(e0.x) << 2) + q]);
    a0.x += e0.y * v0.x; a0.y += e0.y * v0.y; a0.z += e0.y * v0.z; a0.w += e0.y * v0.w;
  }
  float4 acc = make_float4(a0.x + a1.x, a0.y + a1.y, a0.z + a1.z, a0.w + a1.w);
  if (bias) {
    float4 bb = ((const float4*)bias)[q];
    acc = make_float4(fmaxf(acc.x + bb.x, 0.f), fmaxf(acc.y + bb.y, 0.f),
                      fmaxf(acc.z + bb.z, 0.f), fmaxf(acc.w + bb.w, 0.f));
  }
  out[(r << 2) + q] = acc;
}

// ---------------- GEMM1: y[k][n][16] = (x * invrs[r]) @ W1[k] ----------------
// 256 thr, 128 rows x 64 cols, thread tile 8x4; forced 4 blocks/SM (<=64 regs).
__global__ __launch_bounds__(256, 4) void k_gemm1(
    const float* __restrict__ x, const float* __restrict__ W1,
    const float* __restrict__ invrs, float* __restrict__ y, int n) {
  __shared__ float Ws[128][64];
  __shared__ float Xs[128][16];
  int tid = threadIdx.x;
  int rowBase = blockIdx.x * 128;
  for (int s = tid; s < 8192; s += 256) {
    int d = s >> 6, c = s & 63;
    Ws[d][c] = W1[(((c >> 4) << 7) | d) * 16 + (c & 15)];
  }
  float4 acc[8];
  #pragma unroll
  for (int i = 0; i < 8; i++) acc[i] = make_float4(0.f, 0.f, 0.f, 0.f);
  int cg = tid & 15, rg = tid >> 4;
  const float4* x4 = (const float4*)x;
  for (int ch = 0; ch < 8; ch++) {
    __syncthreads();
    for (int s = tid; s < 512; s += 256) {
      int r = s >> 2, d4 = s & 3;
      int row = rowBase + r;
      float4 vv = make_float4(0.f, 0.f, 0.f, 0.f);
      if (row < n) vv = x4[row * 32 + (ch << 2) + d4];
      *(float4*)&Xs[r][d4 << 2] = vv;
    }
    __syncthreads();
    #pragma unroll
    for (int dq = 0; dq < 4; dq++) {
      int d0 = (ch << 4) + (dq << 2);
      float4 w0 = *(const float4*)&Ws[d0 + 0][cg << 2];
      float4 w1 = *(const float4*)&Ws[d0 + 1][cg << 2];
      float4 w2 = *(const float4*)&Ws[d0 + 2][cg << 2];
      float4 w3 = *(const float4*)&Ws[d0 + 3][cg << 2];
      #pragma unroll
      for (int i = 0; i < 8; i++) {
        float4 xv = *(const float4*)&Xs[(rg << 3) + i][dq << 2];
        acc[i].x += xv.x * w0.x + xv.y * w1.x + xv.z * w2.x + xv.w * w3.x;
        acc[i].y += xv.x * w0.y + xv.y * w1.y + xv.z * w2.y + xv.w * w3.y;
        acc[i].z += xv.x * w0.z + xv.y * w1.z + xv.z * w2.z + xv.w * w3.z;
        acc[i].w += xv.x * w0.w + xv.y * w1.w + xv.z * w2.w + xv.w * w3.w;
      }
    }
  }
  int k = cg >> 2;
  int f = (cg & 3) << 2;
  #pragma unroll
  for (int i = 0; i < 8; i++) {
    int r = rowBase + (rg << 3) + i;
    if (r < n) {
      float sc = __ldg(&invrs[r]);
      float4 o = make_float4(acc[i].x * sc, acc[i].y * sc, acc[i].z * sc, acc[i].w * sc);
      *(float4*)&y[(k * n + r) * 16 + f] = o;
    }
  }
}

// ---------------- GEMM2: out[n][64] = sum_k G[k][n][:] @ W2[k] + b2 ----------------
__global__ __launch_bounds__(256) void k_gemm2(
    const float* __restrict__ G, const float* __restrict__ W2,
    const float* __restrict__ b2, float* __restrict__ out, int n) {
  __shared__ float Ws[64][64];
  __shared__ float Gs[128][36];
  int tid = threadIdx.x;
  int rowBase = blockIdx.x * 128;
  for (int s = tid; s < 4096; s += 256) ((float*)Ws)[s] = W2[s];
  float4 acc[8];
  #pragma unroll
  for (int i = 0; i < 8; i++) acc[i] = make_float4(0.f, 0.f, 0.f, 0.f);
  int cg = tid & 15, rg = tid >> 4;
  for (int ch = 0; ch < 2; ch++) {
    __syncthreads();
    for (int s = tid; s < 1024; s += 256) {
      int kk = s >> 9, rem = s & 511;
      int r = rem >> 2, f4 = rem & 3;
      int row = rowBase + r;
      float4 vv = make_float4(0.f, 0.f, 0.f, 0.f);
      if (row < n) vv = *(const float4*)&G[(((ch << 1) | kk) * n + row) * 16 + (f4 << 2)];
      *(float4*)&Gs[r][(kk << 4) | (f4 << 2)] = vv;
    }
    __syncthreads();
    #pragma unroll
    for (int dq = 0; dq < 8; dq++) {
      int d0 = (ch << 5) + (dq << 2);
      float4 w0 = *(const float4*)&Ws[d0 + 0][cg << 2];
      float4 w1 = *(const float4*)&Ws[d0 + 1][cg << 2];
      float4 w2 = *(const float4*)&Ws[d0 + 2][cg << 2];
      float4 w3 = *(const float4*)&Ws[d0 + 3][cg << 2];
      #pragma unroll
      for (int i = 0; i < 8; i++) {
        float4 gv = *(const float4*)&Gs[(rg << 3) + i][dq << 2];
        acc[i].x += gv.x * w0.x + gv.y * w1.x + gv.z * w2.x + gv.w * w3.x;
        acc[i].y += gv.x * w0.y + gv.y * w1.y + gv.z * w2.y + gv.w * w3.y;
        acc[i].z += gv.x * w0.z + gv.y * w1.z + gv.z * w2.z + gv.w * w3.z;
        acc[i].w += gv.x * w0.w + gv.y * w1.w + gv.z * w2.w + gv.w * w3.w;
      }
    }
  }
  float4 bb = *(const float4*)&b2[cg << 2];
  #pragma unroll
  for (int i = 0; i < 8; i++) {
    int r = rowBase + (rg << 3) + i;
    if (r < n) {
      *(float4*)&out[r * 64 + (cg << 2)] = make_float4(
          acc[i].x + bb.x, acc[i].y + bb.y, acc[i].z + bb.z, acc[i].w + bb.w);
    }
  }
}

// ---------------- launch ----------------
extern "C" void kernel_launch(void* const* d_in, const int* in_sizes, int n_in,
                              void* d_out, int out_size) {
  (void)n_in; (void)out_size;
  const float* x  = (const float*)d_in[0];
  const int*   ei = (const int*)d_in[1];
  const float* W1 = (const float*)d_in[2];
  const float* b1 = (const float*)d_in[3];
  const float* W2 = (const float*)d_in[4];
  const float* b2 = (const float*)d_in[5];
  float* out = (float*)d_out;
  int n = in_sizes[0] / 128;
  int E = in_sizes[1] / 2;

  int *cnt, *rp, *base;
  float *dinv, *invrs, *y, *t, *u, *G;
  float2* csr;
  cudaGetSymbolAddress((void**)&cnt,   g_cnt);
  cudaGetSymbolAddress((void**)&rp,    g_rp);
  cudaGetSymbolAddress((void**)&base,  g_base);
  cudaGetSymbolAddress((void**)&dinv,  g_dinv);
  cudaGetSymbolAddress((void**)&invrs, g_invrs);
  cudaGetSymbolAddress((void**)&csr,   g_csr);
  cudaGetSymbolAddress((void**)&y,     g_y);
  cudaGetSymbolAddress((void**)&t,     g_t);
  cudaGetSymbolAddress((void**)&u,     g_u);
  cudaGetSymbolAddress((void**)&G,     g_G);

  const int TB = 256;
  int gN  = (n + TB - 1) / TB;
  int gE  = (E + TB - 1) / TB;
  int gE2 = (E / 2 + TB - 1) / TB;
  int gR4 = (n * 4 + TB - 1) / TB;
  int gW  = (n * 32 + TB - 1) / TB;
  int gG  = (n + 127) / 128;
  int nb  = (n + 1023) / 1024;

  // CSR build prologue + rowsum
  k_zero1<<<gN, TB>>>(cnt, base, n);          // #1
  k_hist<<<gE, TB>>>(ei, cnt, E);             // #2
  k_invrs<<<gW, TB>>>(x, invrs, n);           // #3
  // launch #4 -> profiled: layer-1 projections
  k_gemm1<<<gG, 256>>>(x, W1, invrs, y, n);   // #4
  k_scan1<<<nb, 1024>>>(cnt, rp, base, dinv, n);
  k_fill<<<gE2, TB>>>(ei, dinv, rp, csr, E);

  // layer-1 Horner: G0 = relu(y0 + A(y1 + A(y2 + A*y3)) + b1)
  k_spmm<<<gR4, TB>>>(rp, cnt, csr, (const float4*)(y + 3 * n * 16),
                      (const float4*)(y + 2 * n * 16), nullptr, (float4*)t, n);
  k_spmm<<<gR4, TB>>>(rp, cnt, csr, (const float4*)t,
                      (const float4*)(y + 1 * n * 16), nullptr, (float4*)u, n);
  k_spmm<<<gR4, TB>>>(rp, cnt, csr, (const float4*)u,
                      (const float4*)y, b1, (float4*)G, n);

  // layer-2 hops: G[k+1] = A * G[k]
  for (int k = 0; k < 3; k++) {
    k_spmm<<<gR4, TB>>>(rp, cnt, csr, (const float4*)(G + k * n * 16),
                        nullptr, nullptr, (float4*)(G + (k + 1) * n * 16), n);
  }

  // combine + bias
  k_gemm2<<<gG, 256>>>(G, W2, b2, out, n);
}

// round 7
// speedup vs baseline: 1.3270x; 1.0279x over previous
#include <cuda_runtime.h>
#include <math.h>

#define NMAX 50000
#define EMAX 800000

// ---------------- scratch (no allocation allowed) ----------------
__device__ __align__(16) int   g_cnt[NMAX];        // in-degree (counting-sort hist)
__device__ __align__(16) int   g_rp[NMAX];         // CSR row ptr; fill advances it to row END
__device__ int                 g_base;             // global edge counter for block bases
__device__ __align__(16) float g_dinv[NMAX];
__device__ __align__(16) float g_invrs[NMAX];
__device__ __align__(16) float2 g_csr[EMAX];       // (src bits, weight)
__device__ __align__(16) float g_y[4 * NMAX * 16]; // layer-1 projections y_k
__device__ __align__(16) float g_t[NMAX * 16];
__device__ __align__(16) float g_u[NMAX * 16];
__device__ __align__(16) float g_G[4 * NMAX * 16]; // layer-2 hops

// ---------------- CSR build ----------------
__global__ void k_zero1(int* __restrict__ a, int* __restrict__ base, int n) {
  int i = blockIdx.x * blockDim.x + threadIdx.x;
  if (i < n) a[i] = 0;
  if (i == 0) *base = 0;
}

__global__ void k_hist(const int* __restrict__ ei, int* __restrict__ cnt, int E) {
  int e = blockIdx.x * blockDim.x + threadIdx.x;
  if (e < E) atomicAdd(&cnt[ei[E + e]], 1);
}

// warp per row: inv_rowsum = 1 / max(sum(x_row), 1e-8)
__global__ void k_invrs(const float* __restrict__ x, float* __restrict__ invrs, int n) {
  int w = (blockIdx.x * blockDim.x + threadIdx.x) >> 5;
  int lane = threadIdx.x & 31;
  if (w >= n) return;
  const float4* x4 = (const float4*)x;
  float4 v = x4[w * 32 + lane];
  float s = v.x + v.y + v.z + v.w;
  #pragma unroll
  for (int o = 16; o; o >>= 1) s += __shfl_xor_sync(0xffffffffu, s, o);
  if (lane == 0) invrs[w] = 1.0f / fmaxf(s, 1e-8f);
}

// per-1024-block exclusive scan (warp shuffles) + atomic block base -> FINAL rp.
// Also emits dinv. Block ordering in csr space is irrelevant.
__global__ __launch_bounds__(1024) void k_scan1(const int* __restrict__ cnt,
                                                int* __restrict__ rp,
                                                int* __restrict__ base,
                                                float* __restrict__ dinv, int n) {
  __shared__ int ws[32];
  __shared__ int blockBase;
  int t = threadIdx.x;
  int i = blockIdx.x * 1024 + t;
  int c = (i < n) ? cnt[i] : 0;
  if (i < n) dinv[i] = (c > 0) ? rsqrtf((float)c) : 0.f;
  int s = c;
  #pragma unroll
  for (int o = 1; o < 32; o <<= 1) {
    int p = __shfl_up_sync(0xffffffffu, s, o);
    if ((t & 31) >= o) s += p;
  }
  if ((t & 31) == 31) ws[t >> 5] = s;
  __syncthreads();
  if (t < 32) {
    int b = ws[t];
    int sb = b;
    #pragma unroll
    for (int o = 1; o < 32; o <<= 1) {
      int p = __shfl_up_sync(0xffffffffu, sb, o);
      if (t >= o) sb += p;
    }
    ws[t] = sb - b;
    if (t == 31) blockBase = atomicAdd(base, sb);
  }
  __syncthreads();
  if (i < n) rp[i] = blockBase + (s - c) + ws[t >> 5];
}

// fill CSR entries: (src, dinv[src]*dinv[dst]) into dst buckets.
// rp doubles as the fill cursor; after this kernel rp[d] = end of row d.
__global__ void k_fill(const int* __restrict__ ei, const float* __restrict__ dinv,
                       int* __restrict__ rp, float2* __restrict__ csr, int E) {
  int e = (blockIdx.x * blockDim.x + threadIdx.x) * 2;
  if (e >= E) return;
  int s0 = ei[e];
  int d0 = ei[E + e];
  float w0 = dinv[s0] * dinv[d0];
  int p0 = atomicAdd(&rp[d0], 1);
  if (e + 1 < E) {
    int s1 = ei[e + 1];
    int d1 = ei[E + e + 1];
    float w1 = dinv[s1] * dinv[d1];
    int p1 = atomicAdd(&rp[d1], 1);
    csr[p0] = make_float2(__int_as_float(s0), w0);
    csr[p1] = make_float2(__int_as_float(s1), w1);
  } else {
    csr[p0] = make_float2(__int_as_float(s0), w0);
  }
}

// ---------------- gather SpMM: out[r] = epi(init[r] + sum_e w_e * in[src_e]) ----------------
// rp[r] is the row END (post-fill); start = rp[r] - cnt[r].
__global__ __launch_bounds__(256) void k_spmm(
    const int* __restrict__ rp, const int* __restrict__ cnt,
    const float2* __restrict__ csr, const float4* __restrict__ in,
    const float4* __restrict__ init, const float* __restrict__ bias,
    float4* __restrict__ out, int n) {
  int idx = blockIdx.x * blockDim.x + threadIdx.x;
  int r = idx >> 2;
  if (r >= n) return;
  int q = idx & 3;
  int len = __ldg(&cnt[r]);
  int start = __ldg(&rp[r]) - len;
  float4 a0 = make_float4(0.f, 0.f, 0.f, 0.f);
  float4 a1 = make_float4(0.f, 0.f, 0.f, 0.f);
  if (init) a0 = init[(r << 2) + q];
  int i = 0;
  for (; i + 8 <= len; i += 8) {
    float2 e0 = __ldg(&csr[start + i + 0]);
    float2 e1 = __ldg(&csr[start + i + 1]);
    float2 e2 = __ldg(&csr[start + i + 2]);
    float2 e3 = __ldg(&csr[start + i + 3]);
    float2 e4 = __ldg(&csr[start + i + 4]);
    float2 e5 = __ldg(&csr[start + i + 5]);
    float2 e6 = __ldg(&csr[start + i + 6]);
    float2 e7 = __ldg(&csr[start + i + 7]);
    float4 v0 = __ldg(&in[(__float_as_int(e0.x) << 2) + q]);
    float4 v1 = __ldg(&in[(__float_as_int(e1.x) << 2) + q]);
    float4 v2 = __ldg(&in[(__float_as_int(e2.x) << 2) + q]);
    float4 v3 = __ldg(&in[(__float_as_int(e3.x) << 2) + q]);
    float4 v4 = __ldg(&in[(__float_as_int(e4.x) << 2) + q]);
    float4 v5 = __ldg(&in[(__float_as_int(e5.x) << 2) + q]);
    float4 v6 = __ldg(&in[(__float_as_int(e6.x) << 2) + q]);
    float4 v7 = __ldg(&in[(__float_as_int(e7.x) << 2) + q]);
    a0.x += e0.y * v0.x; a0.y += e0.y * v0.y; a0.z += e0.y * v0.z; a0.w += e0.y * v0.w;
    a1.x += e1.y * v1.x; a1.y += e1.y * v1.y; a1.z += e1.y * v1.z; a1.w += e1.y * v1.w;
    a0.x += e2.y * v2.x; a0.y += e2.y * v2.y; a0.z += e2.y * v2.z; a0.w += e2.y * v2.w;
    a1.x += e3.y * v3.x; a1.y += e3.y * v3.y; a1.z += e3.y * v3.z; a1.w += e3.y * v3.w;
    a0.x += e4.y * v4.x; a0.y += e4.y * v4.y; a0.z += e4.y * v4.z; a0.w += e4.y * v4.w;
    a1.x += e5.y * v5.x; a1.y += e5.y * v5.y; a1.z += e5.y * v5.z; a1.w += e5.y * v5.w;
    a0.x += e6.y * v6.x; a0.y += e6.y * v6.y; a0.z += e6.y * v6.z; a0.w += e6.y * v6.w;
    a1.x += e7.y * v7.x; a1.y += e7.y * v7.y; a1.z += e7.y * v7.z; a1.w += e7.y * v7.w;
  }
  for (; i + 4 <= len; i += 4) {
    float2 e0 = __ldg(&csr[start + i + 0]);
    float2 e1 = __ldg(&csr[start + i + 1]);
    float2 e2 = __ldg(&csr[start + i + 2]);
    float2 e3 = __ldg(&csr[start + i + 3]);
    float4 v0 = __ldg(&in[(__float_as_int(e0.x) << 2) + q]);
    float4 v1 = __ldg(&in[(__float_as_int(e1.x) << 2) + q]);
    float4 v2 = __ldg(&in[(__float_as_int(e2.x) << 2) + q]);
    float4 v3 = __ldg(&in[(__float_as_int(e3.x) << 2) + q]);
    a0.x += e0.y * v0.x; a0.y += e0.y * v0.y; a0.z += e0.y * v0.z; a0.w += e0.y * v0.w;
    a1.x += e1.y * v1.x; a1.y += e1.y * v1.y; a1.z += e1.y * v1.z; a1.w += e1.y * v1.w;
    a0.x += e2.y * v2.x; a0.y += e2.y * v2.y; a0.z += e2.y * v2.z; a0.w += e2.y * v2.w;
    a1.x += e3.y * v3.x; a1.y += e3.y * v3.y; a1.z += e3.y * v3.z; a1.w += e3.y * v3.w;
  }
  for (; i < len; i++) {
    float2 e0 = __ldg(&csr[start + i]);
    float4 v0 = __ldg(&in[(__float_as_int(e0.x) << 2) + q]);
    a0.x += e0.y * v0.x; a0.y += e0.y * v0.y; a0.z += e0.y * v0.z; a0.w += e0.y * v0.w;
  }
  float4 acc = make_float4(a0.x + a1.x, a0.y + a1.y, a0.z + a1.z, a0.w + a1.w);
  if (bias) {
    float4 bb = ((const float4*)bias)[q];
    acc = make_float4(fmaxf(acc.x + bb.x, 0.f), fmaxf(acc.y + bb.y, 0.f),
                      fmaxf(acc.z + bb.z, 0.f), fmaxf(acc.w + bb.w, 0.f));
  }
  out[(r << 2) + q] = acc;
}

// ---------------- GEMM1: y[k][n][16] = (x * invrs[r]) @ W1[k] ----------------
// 64-row x 64-col tiles, 256 threads, 4x4 thread tile -> grid 2x bigger than
// the old 128-row version: ~5.3 blocks/SM, enough warps to hide LDS latency.
__global__ __launch_bounds__(256) void k_gemm1(
    const float* __restrict__ x, const float* __restrict__ W1,
    const float* __restrict__ invrs, float* __restrict__ y, int n) {
  __shared__ float Ws[128][64];   // Ws[d][k*16+f]
  __shared__ float Xs[64][16];    // rows x d-chunk
  int tid = threadIdx.x;
  int rowBase = blockIdx.x * 64;
  for (int s = tid; s < 8192; s += 256) {
    int d = s >> 6, c = s & 63;
    Ws[d][c] = W1[(((c >> 4) << 7) | d) * 16 + (c & 15)];
  }
  float4 acc[4];
  #pragma unroll
  for (int i = 0; i < 4; i++) acc[i] = make_float4(0.f, 0.f, 0.f, 0.f);
  int cg = tid & 15, rg = tid >> 4;
  const float4* x4 = (const float4*)x;
  for (int ch = 0; ch < 8; ch++) {
    __syncthreads();
    {
      int r = tid >> 2, d4 = tid & 3;
      int row = rowBase + r;
      float4 vv = make_float4(0.f, 0.f, 0.f, 0.f);
      if (row < n) vv = x4[row * 32 + (ch << 2) + d4];
      *(float4*)&Xs[r][d4 << 2] = vv;
    }
    __syncthreads();
    #pragma unroll
    for (int dq = 0; dq < 4; dq++) {
      int d0 = (ch << 4) + (dq << 2);
      float4 w0 = *(const float4*)&Ws[d0 + 0][cg << 2];
      float4 w1 = *(const float4*)&Ws[d0 + 1][cg << 2];
      float4 w2 = *(const float4*)&Ws[d0 + 2][cg << 2];
      float4 w3 = *(const float4*)&Ws[d0 + 3][cg << 2];
      #pragma unroll
      for (int i = 0; i < 4; i++) {
        float4 xv = *(const float4*)&Xs[(rg << 2) + i][dq << 2];
        acc[i].x += xv.x * w0.x + xv.y * w1.x + xv.z * w2.x + xv.w * w3.x;
        acc[i].y += xv.x * w0.y + xv.y * w1.y + xv.z * w2.y + xv.w * w3.y;
        acc[i].z += xv.x * w0.z + xv.y * w1.z + xv.z * w2.z + xv.w * w3.z;
        acc[i].w += xv.x * w0.w + xv.y * w1.w + xv.z * w2.w + xv.w * w3.w;
      }
    }
  }
  int k = cg >> 2;
  int f = (cg & 3) << 2;
  #pragma unroll
  for (int i = 0; i < 4; i++) {
    int r = rowBase + (rg << 2) + i;
    if (r < n) {
      float sc = __ldg(&invrs[r]);
      float4 o = make_float4(acc[i].x * sc, acc[i].y * sc, acc[i].z * sc, acc[i].w * sc);
      *(float4*)&y[(k * n + r) * 16 + f] = o;
    }
  }
}

// ---------------- GEMM2: out[n][64] = sum_k G[k][n][:] @ W2[k] + b2 ----------------
// 64-row tiles, 4x4 thread tile (same retile as gemm1).
__global__ __launch_bounds__(256) void k_gemm2(
    const float* __restrict__ G, const float* __restrict__ W2,
    const float* __restrict__ b2, float* __restrict__ out, int n) {
  __shared__ float Ws[64][64];    // W2 already [k*16+d][64] row-major
  __shared__ float Gs[64][36];    // rows x 32-dim chunk, padded
  int tid = threadIdx.x;
  int rowBase = blockIdx.x * 64;
  for (int s = tid; s < 4096; s += 256) ((float*)Ws)[s] = W2[s];
  float4 acc[4];
  #pragma unroll
  for (int i = 0; i < 4; i++) acc[i] = make_float4(0.f, 0.f, 0.f, 0.f);
  int cg = tid & 15, rg = tid >> 4;
  for (int ch = 0; ch < 2; ch++) {
    __syncthreads();
    #pragma unroll
    for (int s0 = 0; s0 < 2; s0++) {
      int s = s0 * 256 + tid;
      int kk = s >> 8, rem = s & 255;
      int r = rem >> 2, f4 = rem & 3;
      int row = rowBase + r;
      float4 vv = make_float4(0.f, 0.f, 0.f, 0.f);
      if (row < n) vv = *(const float4*)&G[(((ch << 1) | kk) * n + row) * 16 + (f4 << 2)];
      *(float4*)&Gs[r][(kk << 4) | (f4 << 2)] = vv;
    }
    __syncthreads();
    #pragma unroll
    for (int dq = 0; dq < 8; dq++) {
      int d0 = (ch << 5) + (dq << 2);
      float4 w0 = *(const float4*)&Ws[d0 + 0][cg << 2];
      float4 w1 = *(const float4*)&Ws[d0 + 1][cg << 2];
      float4 w2 = *(const float4*)&Ws[d0 + 2][cg << 2];
      float4 w3 = *(const float4*)&Ws[d0 + 3][cg << 2];
      #pragma unroll
      for (int i = 0; i < 4; i++) {
        float4 gv = *(const float4*)&Gs[(rg << 2) + i][dq << 2];
        acc[i].x += gv.x * w0.x + gv.y * w1.x + gv.z * w2.x + gv.w * w3.x;
        acc[i].y += gv.x * w0.y + gv.y * w1.y + gv.z * w2.y + gv.w * w3.y;
        acc[i].z += gv.x * w0.z + gv.y * w1.z + gv.z * w2.z + gv.w * w3.z;
        acc[i].w += gv.x * w0.w + gv.y * w1.w + gv.z * w2.w + gv.w * w3.w;
      }
    }
  }
  float4 bb = *(const float4*)&b2[cg << 2];
  #pragma unroll
  for (int i = 0; i < 4; i++) {
    int r = rowBase + (rg << 2) + i;
    if (r < n) {
      *(float4*)&out[r * 64 + (cg << 2)] = make_float4(
          acc[i].x + bb.x, acc[i].y + bb.y, acc[i].z + bb.z, acc[i].w + bb.w);
    }
  }
}

// ---------------- launch ----------------
extern "C" void kernel_launch(void* const* d_in, const int* in_sizes, int n_in,
                              void* d_out, int out_size) {
  (void)n_in; (void)out_size;
  const float* x  = (const float*)d_in[0];
  const int*   ei = (const int*)d_in[1];
  const float* W1 = (const float*)d_in[2];
  const float* b1 = (const float*)d_in[3];
  const float* W2 = (const float*)d_in[4];
  const float* b2 = (const float*)d_in[5];
  float* out = (float*)d_out;
  int n = in_sizes[0] / 128;
  int E = in_sizes[1] / 2;

  int *cnt, *rp, *base;
  float *dinv, *invrs, *y, *t, *u, *G;
  float2* csr;
  cudaGetSymbolAddress((void**)&cnt,   g_cnt);
  cudaGetSymbolAddress((void**)&rp,    g_rp);
  cudaGetSymbolAddress((void**)&base,  g_base);
  cudaGetSymbolAddress((void**)&dinv,  g_dinv);
  cudaGetSymbolAddress((void**)&invrs, g_invrs);
  cudaGetSymbolAddress((void**)&csr,   g_csr);
  cudaGetSymbolAddress((void**)&y,     g_y);
  cudaGetSymbolAddress((void**)&t,     g_t);
  cudaGetSymbolAddress((void**)&u,     g_u);
  cudaGetSymbolAddress((void**)&G,     g_G);

  const int TB = 256;
  int gN  = (n + TB - 1) / TB;
  int gE  = (E + TB - 1) / TB;
  int gE2 = (E / 2 + TB - 1) / TB;
  int gR4 = (n * 4 + TB - 1) / TB;
  int gW  = (n * 32 + TB - 1) / TB;
  int gG  = (n + 63) / 64;
  int nb  = (n + 1023) / 1024;

  // CSR build prologue + rowsum
  k_zero1<<<gN, TB>>>(cnt, base, n);          // #1
  k_hist<<<gE, TB>>>(ei, cnt, E);             // #2
  k_invrs<<<gW, TB>>>(x, invrs, n);           // #3
  // launch #4 -> profiled: layer-1 projections
  k_gemm1<<<gG, 256>>>(x, W1, invrs, y, n);   // #4
  k_scan1<<<nb, 1024>>>(cnt, rp, base, dinv, n);
  k_fill<<<gE2, TB>>>(ei, dinv, rp, csr, E);

  // layer-1 Horner: G0 = relu(y0 + A(y1 + A(y2 + A*y3)) + b1)
  k_spmm<<<gR4, TB>>>(rp, cnt, csr, (const float4*)(y + 3 * n * 16),
                      (const float4*)(y + 2 * n * 16), nullptr, (float4*)t, n);
  k_spmm<<<gR4, TB>>>(rp, cnt, csr, (const float4*)t,
                      (const float4*)(y + 1 * n * 16), nullptr, (float4*)u, n);
  k_spmm<<<gR4, TB>>>(rp, cnt, csr, (const float4*)u,
                      (const float4*)y, b1, (float4*)G, n);

  // layer-2 hops: G[k+1] = A * G[k]
  for (int k = 0; k < 3; k++) {
    k_spmm<<<gR4, TB>>>(rp, cnt, csr, (const float4*)(G + k * n * 16),
                        nullptr, nullptr, (float4*)(G + (k + 1) * n * 16), n);
  }

  // combine + bias
  k_gemm2<<<gG, 256>>>(G, W2, b2, out, n);
}